// round 15
// baseline (speedup 1.0000x reference)
#include <cuda_runtime.h>
#include <cuda_fp16.h>
#include <math.h>
#include <stdint.h>

// Problem constants
#define T      512
#define HDIM   2048
#define NE     32
#define TOPK   8
#define IDIM   1408
#define NGRP   8
#define TKG    4
#define CAP    256
#define RSF    2.5f
#define ISH    2816

// k64-stage SMEM geometry (fp16):
//   A [128 rows][64 k] : 128B data + 16B pad = 144B row stride
//   B [64 k][128 n]    : 256B data + 16B pad = 272B row stride
#define RSA   144
#define RSB   272
#define A_STG (128 * RSA)     // 18432
#define B_STG (64 * RSB)      // 17408
#define SMEM_SZ (2 * (A_STG + B_STG))   // 71680

// Merged-grid block counts
#define FUSED_ROUTED_BLKS (22 * 2 * 32)   // 1408
#define FUSED_TOTAL_BLKS  (FUSED_ROUTED_BLKS + 44 * 4)   // +176 shared
#define PLAIN_ROUTED_BLKS (16 * 2 * 32)   // 1024
#define PLAIN_TOTAL_BLKS  (PLAIN_ROUTED_BLKS + 16 * 4)   // +64 shared

// ---------------- device scratch ----------------
__device__ int    g_topk_ids[T * TOPK];
__device__ float  g_topk_w[T * TOPK];
__device__ int    g_assign_slot[T * TOPK];
__device__ int    g_slot_token[NE * CAP];
__device__ int    g_counts[NE];
__device__ __half g_xh[T * HDIM];
__device__ __half g_h1[NE * CAP * IDIM];
__device__ __half g_hs[T * ISH];
__device__ float  g_y [NE * CAP * HDIM];

// ---------------- helpers ----------------
__device__ __forceinline__ float silu_mul(float g, float u) {
    return (g / (1.f + expf(-g))) * u;
}
__device__ __forceinline__ void mma_f16(float* c, uint4 a, unsigned b0, unsigned b1) {
    asm("mma.sync.aligned.m16n8k16.row.col.f32.f16.f16.f32 "
        "{%0,%1,%2,%3},{%4,%5,%6,%7},{%8,%9},{%0,%1,%2,%3};"
        : "+f"(c[0]), "+f"(c[1]), "+f"(c[2]), "+f"(c[3])
        : "r"(a.x), "r"(a.y), "r"(a.z), "r"(a.w), "r"(b0), "r"(b1));
}
__device__ __forceinline__ uint4 ldsm4(unsigned addr) {
    uint4 r;
    asm volatile("ldmatrix.sync.aligned.m8n8.x4.shared.b16 {%0,%1,%2,%3}, [%4];"
                 : "=r"(r.x), "=r"(r.y), "=r"(r.z), "=r"(r.w) : "r"(addr));
    return r;
}
__device__ __forceinline__ uint4 ldsm4t(unsigned addr) {
    uint4 r;
    asm volatile("ldmatrix.sync.aligned.m8n8.x4.trans.shared.b16 {%0,%1,%2,%3}, [%4];"
                 : "=r"(r.x), "=r"(r.y), "=r"(r.z), "=r"(r.w) : "r"(addr));
    return r;
}
__device__ __forceinline__ unsigned h2u(__half2 h) {
    unsigned u; asm("mov.b32 %0, %1;" : "=r"(u) : "r"(*(unsigned*)&h)); return u;
}
__device__ __forceinline__ uint2 f4h(float4 v) {
    __half2 a = __floats2half2_rn(v.x, v.y);
    __half2 b = __floats2half2_rn(v.z, v.w);
    return make_uint2(h2u(a), h2u(b));
}
__device__ __forceinline__ void cpa16(unsigned dst, const void* src, unsigned n) {
    asm volatile("cp.async.cg.shared.global [%0], [%1], 16, %2;"
                 :: "r"(dst), "l"(src), "r"(n) : "memory");
}
#define CP_COMMIT() asm volatile("cp.async.commit_group;" ::: "memory")
#define CP_WAIT0()  asm volatile("cp.async.wait_group 0;" ::: "memory")

// ---------------- x -> fp16 ----------------
__global__ void convert_x(const float* __restrict__ x) {
    int i = (blockIdx.x * 256 + threadIdx.x) * 4;
    float4 v = *(const float4*)(x + i);
    uint2 h = f4h(v);
    *(uint2*)(g_xh + i) = h;
}

// ---------------- routing (unchanged, known-good) ----------------
__global__ void routing_kernel(const float* __restrict__ x,
                               const float* __restrict__ gw,
                               const float* __restrict__ bias) {
    int t    = blockIdx.x;
    int tid  = threadIdx.x;
    int lane = tid & 31;
    int wid  = tid >> 5;

    __shared__ float part[8][32];
    const float* xr = x + (long long)t * HDIM;
    float acc = 0.f;
    int h0 = wid * (HDIM / 8);
    for (int h = h0; h < h0 + HDIM / 8; ++h)
        acc += xr[h] * gw[h * NE + lane];
    part[wid][lane] = acc;
    __syncthreads();

    if (wid != 0) return;

    float logit = 0.f;
#pragma unroll
    for (int w = 0; w < 8; ++w) logit += part[w][lane];

    float s  = 1.f / (1.f + expf(-logit));
    float sb = s + bias[lane];

    float p   = __shfl_xor_sync(0xffffffffu, sb, 1);
    float hi  = fmaxf(sb, p), lo = fminf(sb, p);
    float hi2 = __shfl_xor_sync(0xffffffffu, hi, 2);
    float lo2 = __shfl_xor_sync(0xffffffffu, lo, 2);
    float gs  = (hi >= hi2) ? hi + fmaxf(hi2, lo) : hi2 + fmaxf(hi, lo2);

    int g = lane >> 2;
    int grank = 0;
#pragma unroll
    for (int g2 = 0; g2 < NGRP; ++g2) {
        float og = __shfl_sync(0xffffffffu, gs, g2 * 4);
        if (og > gs || (og == gs && g2 < g)) ++grank;
    }
    float cand = (grank < TKG) ? sb : -INFINITY;

    float v = cand;
    int   sel_e = 0; float sel_w = 0.f;
#pragma unroll
    for (int k = 0; k < TOPK; ++k) {
        float bv = v; int bi = lane;
#pragma unroll
        for (int off = 16; off; off >>= 1) {
            float ov = __shfl_xor_sync(0xffffffffu, bv, off);
            int   oi = __shfl_xor_sync(0xffffffffu, bi, off);
            if (ov > bv || (ov == bv && oi < bi)) { bv = ov; bi = oi; }
        }
        float ws = __shfl_sync(0xffffffffu, s, bi);
        if (lane == k)  { sel_e = bi; sel_w = ws; }
        if (lane == bi) v = -INFINITY;
    }

    float wv = (lane < TOPK) ? sel_w : 0.f;
#pragma unroll
    for (int off = 16; off; off >>= 1) wv += __shfl_xor_sync(0xffffffffu, wv, off);
    if (lane < TOPK) {
        g_topk_ids[t * TOPK + lane] = sel_e;
        g_topk_w  [t * TOPK + lane] = sel_w / wv * RSF;
    }
}

// ---------------- capacity ranking (unchanged) ----------------
__global__ void rank_kernel() {
    int w    = threadIdx.x >> 5;
    int lane = threadIdx.x & 31;
    int cnt  = 0;
    for (int i0 = 0; i0 < T * TOPK; i0 += 32) {
        int i = i0 + lane;
        int e = g_topk_ids[i];
        bool m = (e == w);
        unsigned mask = __ballot_sync(0xffffffffu, m);
        if (m) {
            int r = cnt + __popc(mask & ((1u << lane) - 1u));
            if (r < CAP) {
                g_assign_slot[i] = w * CAP + r;
                g_slot_token[w * CAP + r] = i >> 3;
            } else {
                g_assign_slot[i] = -1;
            }
        }
        cnt += __popc(mask);
    }
    if (lane == 0) g_counts[w] = min(cnt, CAP);
}

// ============================================================================
// MERGED fused gate/up fp16 GEMM (routed + shared). k64 stages, 2-stage SMEM.
// Block M=128, N=64g+64u. 8 warps 4(m)x2(n); warp m32 x (n32g+n32u).
// ============================================================================
__global__ void __launch_bounds__(256, 2)
gemm_fused_all(const float* __restrict__ w13, const float* __restrict__ sgu) {
    extern __shared__ __align__(16) char sm[];

    const int bid = blockIdx.x;
    const bool routed = bid < FUSED_ROUTED_BLKS;
    int e, nt, mt, Mloc, ldb, up_off, ldc;
    const float* Bp;
    __half* Cp;
    if (routed) {
        e = bid / 44; int r = bid % 44;
        nt = r % 22; mt = r / 22;
        Mloc = g_counts[e];
        Bp = w13 + (long long)e * HDIM * 2 * IDIM;
        ldb = 2 * IDIM; up_off = IDIM; ldc = IDIM;
        Cp = g_h1 + (long long)e * CAP * IDIM;
    } else {
        e = 0; int r = bid - FUSED_ROUTED_BLKS;
        nt = r % 44; mt = r / 44;
        Mloc = T;
        Bp = sgu;
        ldb = 2 * ISH; up_off = ISH; ldc = ISH;
        Cp = g_hs;
    }
    const int m0 = mt * 128;
    if (m0 >= Mloc) return;
    const int n0 = nt * 64;
    const int S = HDIM / 64;

    const unsigned smb  = (unsigned)__cvta_generic_to_shared(sm);
    const unsigned smbB = smb + 2 * A_STG;
    const int tid  = threadIdx.x;
    const int lane = tid & 31;
    const int wid  = tid >> 5;
    const int gid  = lane >> 2;
    const int tig  = lane & 3;
    const int mt0  = (wid >> 1) * 2;
    const int wn   = (wid & 1) * 4;

    // A cp.async: row = tid>>1, 64B half = tid&1 (4 chunks of 16B)
    const int arow = tid >> 1;
    const int ah   = tid & 1;
    const int gm   = m0 + arow;
    const bool avl = gm < Mloc;
    int grow;
    if (routed) grow = avl ? g_slot_token[e * CAP + gm] : 0;
    else        grow = avl ? gm : 0;
    const __half* asrc = g_xh + (long long)grow * HDIM + ah * 32;
    const unsigned adst = smb + (unsigned)arow * RSA + (unsigned)ah * 64u;
    const unsigned asz  = avl ? 16u : 0u;

    // B: kk = tid>>2 (0..63), q = tid&3 (0,1 gate halves; 2,3 up halves), 32 cols
    const int kk = tid >> 2;
    const int q  = tid & 3;
    const int bcol = (q < 2) ? (n0 + q * 32) : (up_off + n0 + (q - 2) * 32);
    const float* bsrc = Bp + (long long)kk * ldb + bcol;
    const unsigned bdoff = (unsigned)kk * RSB + (unsigned)q * 64u;

    float accg[2][4][4], accu[2][4][4];
#pragma unroll
    for (int mi = 0; mi < 2; ++mi)
#pragma unroll
        for (int ni = 0; ni < 4; ++ni)
#pragma unroll
            for (int r = 0; r < 4; ++r) { accg[mi][ni][r] = 0.f; accu[mi][ni][r] = 0.f; }

    unsigned aAddr[2], gAddr[2], uAddr[2];
#pragma unroll
    for (int mi = 0; mi < 2; ++mi)
        aAddr[mi] = smb + ((mt0 + mi) * 16 + (lane & 15)) * RSA + (lane >> 4) * 16;
#pragma unroll
    for (int j = 0; j < 2; ++j) {
        gAddr[j] = smbB + (lane & 15) * RSB + (wn + 2 * j) * 16 + (lane >> 4) * 16;
        uAddr[j] = gAddr[j] + 128;
    }

    float4 rb[4];

    auto cpaA = [&](int s, unsigned buf) {
        const unsigned off = buf * A_STG;
        const __half* src = asrc + s * 64;
#pragma unroll
        for (int c = 0; c < 4; ++c) cpa16(adst + off + c * 16, src + c * 8, asz);
        CP_COMMIT();
    };
    auto ldgB = [&](int s, int half) {
        const float* bs = bsrc + (long long)s * 64 * ldb + half * 16;
#pragma unroll
        for (int p = 0; p < 4; ++p) rb[p] = ((const float4*)bs)[p];
    };
    auto stsB = [&](unsigned buf, int half) {
        char* bd = sm + 2 * A_STG + buf * B_STG + bdoff + half * 32;
        uint2 h0 = f4h(rb[0]), h1 = f4h(rb[1]), h2 = f4h(rb[2]), h3 = f4h(rb[3]);
        *(uint4*)(bd)      = make_uint4(h0.x, h0.y, h1.x, h1.y);
        *(uint4*)(bd + 16) = make_uint4(h2.x, h2.y, h3.x, h3.y);
    };

    // prologue: stage 0
    cpaA(0, 0);
    ldgB(0, 0); stsB(0, 0);
    ldgB(0, 1); stsB(0, 1);
    CP_WAIT0();
    __syncthreads();

    for (int s = 0; s < S; ++s) {
        const unsigned buf = s & 1;
        const bool nxt = (s + 1) < S;
        if (nxt) {
            cpaA(s + 1, buf ^ 1);
            ldgB(s + 1, 0);
        }
        const unsigned ao = buf * A_STG, bo = buf * B_STG;
#pragma unroll
        for (int kt = 0; kt < 4; ++kt) {
            if (kt == 2 && nxt) {
                stsB(buf ^ 1, 0);
                ldgB(s + 1, 1);
            }
            const unsigned ka = kt * 32, kb = kt * 16 * RSB;
            uint4 a0 = ldsm4(aAddr[0] + ao + ka);
            uint4 a1 = ldsm4(aAddr[1] + ao + ka);
            uint4 bg0 = ldsm4t(gAddr[0] + bo + kb);
            uint4 bg1 = ldsm4t(gAddr[1] + bo + kb);
            uint4 bu0 = ldsm4t(uAddr[0] + bo + kb);
            uint4 bu1 = ldsm4t(uAddr[1] + bo + kb);
            mma_f16(accg[0][0], a0, bg0.x, bg0.y); mma_f16(accg[0][1], a0, bg0.z, bg0.w);
            mma_f16(accg[0][2], a0, bg1.x, bg1.y); mma_f16(accg[0][3], a0, bg1.z, bg1.w);
            mma_f16(accg[1][0], a1, bg0.x, bg0.y); mma_f16(accg[1][1], a1, bg0.z, bg0.w);
            mma_f16(accg[1][2], a1, bg1.x, bg1.y); mma_f16(accg[1][3], a1, bg1.z, bg1.w);
            mma_f16(accu[0][0], a0, bu0.x, bu0.y); mma_f16(accu[0][1], a0, bu0.z, bu0.w);
            mma_f16(accu[0][2], a0, bu1.x, bu1.y); mma_f16(accu[0][3], a0, bu1.z, bu1.w);
            mma_f16(accu[1][0], a1, bu0.x, bu0.y); mma_f16(accu[1][1], a1, bu0.z, bu0.w);
            mma_f16(accu[1][2], a1, bu1.x, bu1.y); mma_f16(accu[1][3], a1, bu1.z, bu1.w);
        }
        if (nxt) {
            stsB(buf ^ 1, 1);
            CP_WAIT0();
        }
        __syncthreads();
    }

    // epilogue: fp16(silu(g)*u)
#pragma unroll
    for (int mi = 0; mi < 2; ++mi) {
        int rA = m0 + (mt0 + mi) * 16 + gid;
        int rB = rA + 8;
#pragma unroll
        for (int ni = 0; ni < 4; ++ni) {
            int col = n0 + (wn + ni) * 8 + 2 * tig;
            if (rA < Mloc) {
                __half2 h = __floats2half2_rn(
                    silu_mul(accg[mi][ni][0], accu[mi][ni][0]),
                    silu_mul(accg[mi][ni][1], accu[mi][ni][1]));
                *(__half2*)&Cp[(long long)rA * ldc + col] = h;
            }
            if (rB < Mloc) {
                __half2 h = __floats2half2_rn(
                    silu_mul(accg[mi][ni][2], accu[mi][ni][2]),
                    silu_mul(accg[mi][ni][3], accu[mi][ni][3]));
                *(__half2*)&Cp[(long long)rB * ldc + col] = h;
            }
        }
    }
}

// ============================================================================
// MERGED plain fp16 GEMM (routed + shared). k64 stages, 2-stage SMEM.
// Block M=128, N=128. 8 warps 2(m)x4(n); warp m64 x n32.
// ============================================================================
__global__ void __launch_bounds__(256, 2)
gemm_plain_all(const float* __restrict__ w2, const float* __restrict__ sdn,
               float* __restrict__ out) {
    extern __shared__ __align__(16) char sm[];

    const int bid = blockIdx.x;
    const bool routed = bid < PLAIN_ROUTED_BLKS;
    int e, nt, mt, Mloc, lda, ldb, ldc, Kd;
    const float*  Bp;
    const __half* Ap;
    float* Cp;
    if (routed) {
        e = bid / 32; int r = bid % 32;
        nt = r % 16; mt = r / 16;
        Mloc = g_counts[e];
        Ap = g_h1 + (long long)e * CAP * IDIM;  lda = IDIM;
        Bp = w2  + (long long)e * IDIM * HDIM;  ldb = HDIM;
        Cp = g_y + (long long)e * CAP * HDIM;   ldc = HDIM;
        Kd = IDIM;
    } else {
        e = 0; int r = bid - PLAIN_ROUTED_BLKS;
        nt = r % 16; mt = r / 16;
        Mloc = T;
        Ap = g_hs; lda = ISH;
        Bp = sdn;  ldb = HDIM;
        Cp = out;  ldc = HDIM;
        Kd = ISH;
    }
    const int m0 = mt * 128;
    if (m0 >= Mloc) return;
    const int n0 = nt * 128;
    const int S = Kd / 64;

    const unsigned smb  = (unsigned)__cvta_generic_to_shared(sm);
    const unsigned smbB = smb + 2 * A_STG;
    const int tid  = threadIdx.x;
    const int lane = tid & 31;
    const int wid  = tid >> 5;
    const int gid  = lane >> 2;
    const int tig  = lane & 3;
    const int mt0  = (wid >> 2) * 4;
    const int nt0  = (wid & 3) * 4;

    const int arow = tid >> 1;
    const int ah   = tid & 1;
    const int gm   = m0 + arow;
    const bool avl = gm < Mloc;
    const __half* asrc = Ap + (long long)(avl ? gm : 0) * lda + ah * 32;
    const unsigned adst = smb + (unsigned)arow * RSA + (unsigned)ah * 64u;
    const unsigned asz  = avl ? 16u : 0u;

    const int kk = tid >> 2;
    const int q  = tid & 3;
    const float* bsrc = Bp + (long long)kk * ldb + n0 + q * 32;
    const unsigned bdoff = (unsigned)kk * RSB + (unsigned)q * 64u;

    float acc[4][4][4];
#pragma unroll
    for (int mi = 0; mi < 4; ++mi)
#pragma unroll
        for (int ni = 0; ni < 4; ++ni)
#pragma unroll
            for (int r = 0; r < 4; ++r) acc[mi][ni][r] = 0.f;

    unsigned aAddr[4], bAddr[2];
#pragma unroll
    for (int mi = 0; mi < 4; ++mi)
        aAddr[mi] = smb + ((mt0 + mi) * 16 + (lane & 15)) * RSA + (lane >> 4) * 16;
#pragma unroll
    for (int j = 0; j < 2; ++j)
        bAddr[j] = smbB + (lane & 15) * RSB + (nt0 + 2 * j) * 16 + (lane >> 4) * 16;

    float4 rb[4];

    auto cpaA = [&](int s, unsigned buf) {
        const unsigned off = buf * A_STG;
        const __half* src = asrc + s * 64;
#pragma unroll
        for (int c = 0; c < 4; ++c) cpa16(adst + off + c * 16, src + c * 8, asz);
        CP_COMMIT();
    };
    auto ldgB = [&](int s, int half) {
        const float* bs = bsrc + (long long)s * 64 * ldb + half * 16;
#pragma unroll
        for (int p = 0; p < 4; ++p) rb[p] = ((const float4*)bs)[p];
    };
    auto stsB = [&](unsigned buf, int half) {
        char* bd = sm + 2 * A_STG + buf * B_STG + bdoff + half * 32;
        uint2 h0 = f4h(rb[0]), h1 = f4h(rb[1]), h2 = f4h(rb[2]), h3 = f4h(rb[3]);
        *(uint4*)(bd)      = make_uint4(h0.x, h0.y, h1.x, h1.y);
        *(uint4*)(bd + 16) = make_uint4(h2.x, h2.y, h3.x, h3.y);
    };

    cpaA(0, 0);
    ldgB(0, 0); stsB(0, 0);
    ldgB(0, 1); stsB(0, 1);
    CP_WAIT0();
    __syncthreads();

    for (int s = 0; s < S; ++s) {
        const unsigned buf = s & 1;
        const bool nxt = (s + 1) < S;
        if (nxt) {
            cpaA(s + 1, buf ^ 1);
            ldgB(s + 1, 0);
        }
        const unsigned ao = buf * A_STG, bo = buf * B_STG;
#pragma unroll
        for (int kt = 0; kt < 4; ++kt) {
            if (kt == 2 && nxt) {
                stsB(buf ^ 1, 0);
                ldgB(s + 1, 1);
            }
            const unsigned ka = kt * 32, kb = kt * 16 * RSB;
            uint4 af[4];
#pragma unroll
            for (int mi = 0; mi < 4; ++mi) af[mi] = ldsm4(aAddr[mi] + ao + ka);
            uint4 b0 = ldsm4t(bAddr[0] + bo + kb);
            uint4 b1 = ldsm4t(bAddr[1] + bo + kb);
#pragma unroll
            for (int mi = 0; mi < 4; ++mi) {
                mma_f16(acc[mi][0], af[mi], b0.x, b0.y);
                mma_f16(acc[mi][1], af[mi], b0.z, b0.w);
                mma_f16(acc[mi][2], af[mi], b1.x, b1.y);
                mma_f16(acc[mi][3], af[mi], b1.z, b1.w);
            }
        }
        if (nxt) {
            stsB(buf ^ 1, 1);
            CP_WAIT0();
        }
        __syncthreads();
    }

#pragma unroll
    for (int mi = 0; mi < 4; ++mi) {
        int rA = m0 + (mt0 + mi) * 16 + gid;
        int rB = rA + 8;
#pragma unroll
        for (int ni = 0; ni < 4; ++ni) {
            int c0 = n0 + (nt0 + ni) * 8 + 2 * tig;
            if (rA < Mloc)
                *(float2*)&Cp[(long long)rA * ldc + c0] =
                    make_float2(acc[mi][ni][0], acc[mi][ni][1]);
            if (rB < Mloc)
                *(float2*)&Cp[(long long)rB * ldc + c0] =
                    make_float2(acc[mi][ni][2], acc[mi][ni][3]);
        }
    }
}

// ---------------- combine (float4) ----------------
__global__ void combine_kernel(float* __restrict__ out) {
    int t = blockIdx.x;
    __shared__ int   sslot[TOPK];
    __shared__ float sw[TOPK];
    if (threadIdx.x < TOPK) {
        sslot[threadIdx.x] = g_assign_slot[t * TOPK + threadIdx.x];
        sw[threadIdx.x]    = g_topk_w[t * TOPK + threadIdx.x];
    }
    __syncthreads();
    for (int h = threadIdx.x * 4; h < HDIM; h += 256 * 4) {
        float4 acc = *(float4*)&out[(long long)t * HDIM + h];
#pragma unroll
        for (int k = 0; k < TOPK; ++k) {
            int sl = sslot[k];
            if (sl >= 0) {
                float4 y = *(float4*)&g_y[(long long)sl * HDIM + h];
                float w = sw[k];
                acc.x += w * y.x; acc.y += w * y.y;
                acc.z += w * y.z; acc.w += w * y.w;
            }
        }
        *(float4*)&out[(long long)t * HDIM + h] = acc;
    }
}

// ---------------- launch ----------------
extern "C" void kernel_launch(void* const* d_in, const int* in_sizes, int n_in,
                              void* d_out, int out_size) {
    const float* x     = (const float*)d_in[0];
    const float* gw    = (const float*)d_in[2];
    const float* bias  = (const float*)d_in[3];
    const float* w13   = (const float*)d_in[4];
    const float* w2    = (const float*)d_in[5];
    const float* sgu   = (const float*)d_in[6];
    const float* sdn   = (const float*)d_in[7];
    float* out = (float*)d_out;

    cudaFuncSetAttribute(gemm_fused_all,
                         cudaFuncAttributeMaxDynamicSharedMemorySize, SMEM_SZ);
    cudaFuncSetAttribute(gemm_plain_all,
                         cudaFuncAttributeMaxDynamicSharedMemorySize, SMEM_SZ);

    convert_x<<<T * HDIM / 1024, 256>>>(x);
    routing_kernel<<<T, 256>>>(x, gw, bias);
    rank_kernel<<<1, 1024>>>();
    gemm_fused_all<<<FUSED_TOTAL_BLKS, 256, SMEM_SZ>>>(w13, sgu);
    gemm_plain_all<<<PLAIN_TOTAL_BLKS, 256, SMEM_SZ>>>(w2, sdn, out);
    combine_kernel<<<T, 256>>>(out);
}

// round 16
// speedup vs baseline: 1.3066x; 1.3066x over previous
#include <cuda_runtime.h>
#include <cuda_fp16.h>
#include <math.h>
#include <stdint.h>

// Problem constants
#define T      512
#define HDIM   2048
#define NE     32
#define TOPK   8
#define IDIM   1408
#define NGRP   8
#define TKG    4
#define CAP    256
#define RSF    2.5f
#define ISH    2816

// SMEM geometry (fp16): A [128 rows][32k] rows 64B+16 pad; B [32k][128n] rows 256B+16 pad
#define RSA   80
#define RSB   272
#define A_STG (128 * RSA)     // 10240
#define B_STG (32 * RSB)      // 8704

// Tile counts
#define FUSED_ROUTED_TILES (44 * 32)            // 1408 (22 n x 2 m per expert)
#define FUSED_TILES        (FUSED_ROUTED_TILES + 176)   // + shared (44 n x 4 m)
#define PLAIN_ROUTED_TILES (32 * 32)            // 1024 (16 n x 2 m per expert)
#define PLAIN_TILES        (PLAIN_ROUTED_TILES + 64)    // + shared (16 n x 4 m)
#define TOTAL_TILES        (FUSED_TILES + PLAIN_TILES)  // 2672
#define PERSIST_BLKS       296

// ---------------- device scratch ----------------
__device__ int    g_topk_ids[T * TOPK];
__device__ float  g_topk_w[T * TOPK];
__device__ int    g_assign_slot[T * TOPK];
__device__ int    g_slot_token[NE * CAP];
__device__ int    g_counts[NE];
__device__ __half g_xh[T * HDIM];
__device__ __half g_h1[NE * CAP * IDIM];
__device__ __half g_hs[T * ISH];
__device__ float  g_y [NE * CAP * HDIM];
__device__ int    g_queue;
__device__ int    g_done[NE];
__device__ int    g_done_sh;

// ---------------- helpers ----------------
__device__ __forceinline__ float silu_mul(float g, float u) {
    return (g / (1.f + expf(-g))) * u;
}
__device__ __forceinline__ void mma_f16(float* c, uint4 a, unsigned b0, unsigned b1) {
    asm("mma.sync.aligned.m16n8k16.row.col.f32.f16.f16.f32 "
        "{%0,%1,%2,%3},{%4,%5,%6,%7},{%8,%9},{%0,%1,%2,%3};"
        : "+f"(c[0]), "+f"(c[1]), "+f"(c[2]), "+f"(c[3])
        : "r"(a.x), "r"(a.y), "r"(a.z), "r"(a.w), "r"(b0), "r"(b1));
}
__device__ __forceinline__ uint4 ldsm4(unsigned addr) {
    uint4 r;
    asm volatile("ldmatrix.sync.aligned.m8n8.x4.shared.b16 {%0,%1,%2,%3}, [%4];"
                 : "=r"(r.x), "=r"(r.y), "=r"(r.z), "=r"(r.w) : "r"(addr));
    return r;
}
__device__ __forceinline__ uint4 ldsm4t(unsigned addr) {
    uint4 r;
    asm volatile("ldmatrix.sync.aligned.m8n8.x4.trans.shared.b16 {%0,%1,%2,%3}, [%4];"
                 : "=r"(r.x), "=r"(r.y), "=r"(r.z), "=r"(r.w) : "r"(addr));
    return r;
}
__device__ __forceinline__ unsigned h2u(__half2 h) {
    unsigned u; asm("mov.b32 %0, %1;" : "=r"(u) : "r"(*(unsigned*)&h)); return u;
}
__device__ __forceinline__ uint2 f4h(float4 v) {
    __half2 a = __floats2half2_rn(v.x, v.y);
    __half2 b = __floats2half2_rn(v.z, v.w);
    return make_uint2(h2u(a), h2u(b));
}
__device__ __forceinline__ void cpa16(unsigned dst, const void* src, unsigned n) {
    asm volatile("cp.async.cg.shared.global [%0], [%1], 16, %2;"
                 :: "r"(dst), "l"(src), "r"(n) : "memory");
}
#define CP_COMMIT() asm volatile("cp.async.commit_group;" ::: "memory")
#define CP_WAIT0()  asm volatile("cp.async.wait_group 0;" ::: "memory")

// ---------------- x -> fp16 ----------------
__global__ void convert_x(const float* __restrict__ x) {
    int i = (blockIdx.x * 256 + threadIdx.x) * 4;
    float4 v = *(const float4*)(x + i);
    uint2 h = f4h(v);
    *(uint2*)(g_xh + i) = h;
}

// ---------------- routing (unchanged, known-good) ----------------
__global__ void routing_kernel(const float* __restrict__ x,
                               const float* __restrict__ gw,
                               const float* __restrict__ bias) {
    int t    = blockIdx.x;
    int tid  = threadIdx.x;
    int lane = tid & 31;
    int wid  = tid >> 5;

    __shared__ float part[8][32];
    const float* xr = x + (long long)t * HDIM;
    float acc = 0.f;
    int h0 = wid * (HDIM / 8);
    for (int h = h0; h < h0 + HDIM / 8; ++h)
        acc += xr[h] * gw[h * NE + lane];
    part[wid][lane] = acc;
    __syncthreads();

    if (wid != 0) return;

    float logit = 0.f;
#pragma unroll
    for (int w = 0; w < 8; ++w) logit += part[w][lane];

    float s  = 1.f / (1.f + expf(-logit));
    float sb = s + bias[lane];

    float p   = __shfl_xor_sync(0xffffffffu, sb, 1);
    float hi  = fmaxf(sb, p), lo = fminf(sb, p);
    float hi2 = __shfl_xor_sync(0xffffffffu, hi, 2);
    float lo2 = __shfl_xor_sync(0xffffffffu, lo, 2);
    float gs  = (hi >= hi2) ? hi + fmaxf(hi2, lo) : hi2 + fmaxf(hi, lo2);

    int g = lane >> 2;
    int grank = 0;
#pragma unroll
    for (int g2 = 0; g2 < NGRP; ++g2) {
        float og = __shfl_sync(0xffffffffu, gs, g2 * 4);
        if (og > gs || (og == gs && g2 < g)) ++grank;
    }
    float cand = (grank < TKG) ? sb : -INFINITY;

    float v = cand;
    int   sel_e = 0; float sel_w = 0.f;
#pragma unroll
    for (int k = 0; k < TOPK; ++k) {
        float bv = v; int bi = lane;
#pragma unroll
        for (int off = 16; off; off >>= 1) {
            float ov = __shfl_xor_sync(0xffffffffu, bv, off);
            int   oi = __shfl_xor_sync(0xffffffffu, bi, off);
            if (ov > bv || (ov == bv && oi < bi)) { bv = ov; bi = oi; }
        }
        float ws = __shfl_sync(0xffffffffu, s, bi);
        if (lane == k)  { sel_e = bi; sel_w = ws; }
        if (lane == bi) v = -INFINITY;
    }

    float wv = (lane < TOPK) ? sel_w : 0.f;
#pragma unroll
    for (int off = 16; off; off >>= 1) wv += __shfl_xor_sync(0xffffffffu, wv, off);
    if (lane < TOPK) {
        g_topk_ids[t * TOPK + lane] = sel_e;
        g_topk_w  [t * TOPK + lane] = sel_w / wv * RSF;
    }
}

// ---------------- capacity ranking + counter reset ----------------
__global__ void rank_kernel() {
    int tid = threadIdx.x;
    // reset mega-kernel coordination state (fresh every replay)
    if (tid < NE) g_done[tid] = 0;
    if (tid == NE) g_done_sh = 0;
    if (tid == NE + 1) g_queue = 0;

    int w    = tid >> 5;
    int lane = tid & 31;
    int cnt  = 0;
    for (int i0 = 0; i0 < T * TOPK; i0 += 32) {
        int i = i0 + lane;
        int e = g_topk_ids[i];
        bool m = (e == w);
        unsigned mask = __ballot_sync(0xffffffffu, m);
        if (m) {
            int r = cnt + __popc(mask & ((1u << lane) - 1u));
            if (r < CAP) {
                g_assign_slot[i] = w * CAP + r;
                g_slot_token[w * CAP + r] = i >> 3;
            } else {
                g_assign_slot[i] = -1;
            }
        }
        cnt += __popc(mask);
    }
    if (lane == 0) g_counts[w] = min(cnt, CAP);
}

// ============================================================================
// Fused gate/up tile (R13 body). Block M=128, N=64g+64u.
// ============================================================================
__device__ __forceinline__ void fused_tile(char* sm, int tile,
                                           const float* __restrict__ w13,
                                           const float* __restrict__ sgu) {
    const bool routed = tile < FUSED_ROUTED_TILES;
    int e, nt, mt, Mloc, ldb, up_off, ldc;
    const float* Bp;
    __half* Cp;
    if (routed) {
        e = tile / 44; int r = tile % 44;
        nt = r % 22; mt = r / 22;
        Mloc = g_counts[e];
        Bp = w13 + (long long)e * HDIM * 2 * IDIM;
        ldb = 2 * IDIM; up_off = IDIM; ldc = IDIM;
        Cp = g_h1 + (long long)e * CAP * IDIM;
    } else {
        e = 0; int r = tile - FUSED_ROUTED_TILES;
        nt = r % 44; mt = r / 44;
        Mloc = T;
        Bp = sgu;
        ldb = 2 * ISH; up_off = ISH; ldc = ISH;
        Cp = g_hs;
    }
    const int m0 = mt * 128;
    const int n0 = nt * 64;

    if (m0 < Mloc) {
        const unsigned smb  = (unsigned)__cvta_generic_to_shared(sm);
        const unsigned smbB = smb + 2 * A_STG;
        const int tid  = threadIdx.x;
        const int lane = tid & 31;
        const int wid  = tid >> 5;
        const int gid  = lane >> 2;
        const int tig  = lane & 3;
        const int mt0  = (wid >> 1) * 2;
        const int wn   = (wid & 1) * 4;

        const int arow = tid >> 1;
        const int ah   = tid & 1;
        const int gm   = m0 + arow;
        const bool avl = gm < Mloc;
        int grow;
        if (routed) grow = avl ? g_slot_token[e * CAP + gm] : 0;
        else        grow = avl ? gm : 0;
        const __half* asrc = g_xh + (long long)grow * HDIM + ah * 16;
        const unsigned adst = smb + (unsigned)arow * RSA + (unsigned)ah * 32u;
        const unsigned asz  = avl ? 16u : 0u;

        const int kk = tid >> 3;
        const int ng = tid & 7;
        const int bcol = (ng < 4) ? (n0 + ng * 16) : (up_off + n0 + (ng - 4) * 16);
        const float* bsrc = Bp + (long long)kk * ldb + bcol;
        const unsigned bdoff = (unsigned)kk * RSB + (unsigned)ng * 32u;

        float accg[2][4][4], accu[2][4][4];
#pragma unroll
        for (int mi = 0; mi < 2; ++mi)
#pragma unroll
            for (int ni = 0; ni < 4; ++ni)
#pragma unroll
                for (int r = 0; r < 4; ++r) { accg[mi][ni][r] = 0.f; accu[mi][ni][r] = 0.f; }

        unsigned aAddr[2], gAddr[2], uAddr[2];
#pragma unroll
        for (int mi = 0; mi < 2; ++mi)
            aAddr[mi] = smb + ((mt0 + mi) * 16 + (lane & 15)) * RSA + (lane >> 4) * 16;
#pragma unroll
        for (int j = 0; j < 2; ++j) {
            gAddr[j] = smbB + (lane & 15) * RSB + (wn + 2 * j) * 16 + (lane >> 4) * 16;
            uAddr[j] = gAddr[j] + 128;
        }

        const int S = HDIM / 32;
        float4 rb[4];

        cpa16(adst, asrc, asz);
        cpa16(adst + 16, asrc + 8, asz);
        CP_COMMIT();
#pragma unroll
        for (int q = 0; q < 4; ++q) rb[q] = ((const float4*)bsrc)[q];
        {
            char* bd = sm + 2 * A_STG + bdoff;
            uint2 h0 = f4h(rb[0]), h1 = f4h(rb[1]), h2 = f4h(rb[2]), h3 = f4h(rb[3]);
            *(uint4*)(bd)      = make_uint4(h0.x, h0.y, h1.x, h1.y);
            *(uint4*)(bd + 16) = make_uint4(h2.x, h2.y, h3.x, h3.y);
        }
        CP_WAIT0();
        __syncthreads();

        for (int s = 0; s < S; ++s) {
            const unsigned buf = s & 1;
            const bool nxt = (s + 1) < S;
            if (nxt) {
                const unsigned b2 = buf ^ 1;
                const __half* src = asrc + (s + 1) * 32;
                cpa16(adst + b2 * A_STG, src, asz);
                cpa16(adst + b2 * A_STG + 16, src + 8, asz);
                CP_COMMIT();
                const float* bs = bsrc + (long long)(s + 1) * 32 * ldb;
#pragma unroll
                for (int q = 0; q < 4; ++q) rb[q] = ((const float4*)bs)[q];
            }
            const unsigned ao = buf * A_STG, bo = buf * B_STG;
#pragma unroll
            for (int kt = 0; kt < 2; ++kt) {
                const unsigned ka = kt * 32, kb = kt * 16 * RSB;
                uint4 a0 = ldsm4(aAddr[0] + ao + ka);
                uint4 a1 = ldsm4(aAddr[1] + ao + ka);
                uint4 bg0 = ldsm4t(gAddr[0] + bo + kb);
                uint4 bg1 = ldsm4t(gAddr[1] + bo + kb);
                uint4 bu0 = ldsm4t(uAddr[0] + bo + kb);
                uint4 bu1 = ldsm4t(uAddr[1] + bo + kb);
                mma_f16(accg[0][0], a0, bg0.x, bg0.y); mma_f16(accg[0][1], a0, bg0.z, bg0.w);
                mma_f16(accg[0][2], a0, bg1.x, bg1.y); mma_f16(accg[0][3], a0, bg1.z, bg1.w);
                mma_f16(accg[1][0], a1, bg0.x, bg0.y); mma_f16(accg[1][1], a1, bg0.z, bg0.w);
                mma_f16(accg[1][2], a1, bg1.x, bg1.y); mma_f16(accg[1][3], a1, bg1.z, bg1.w);
                mma_f16(accu[0][0], a0, bu0.x, bu0.y); mma_f16(accu[0][1], a0, bu0.z, bu0.w);
                mma_f16(accu[0][2], a0, bu1.x, bu1.y); mma_f16(accu[0][3], a0, bu1.z, bu1.w);
                mma_f16(accu[1][0], a1, bu0.x, bu0.y); mma_f16(accu[1][1], a1, bu0.z, bu0.w);
                mma_f16(accu[1][2], a1, bu1.x, bu1.y); mma_f16(accu[1][3], a1, bu1.z, bu1.w);
            }
            if (nxt) {
                char* bd = sm + 2 * A_STG + (buf ^ 1) * B_STG + bdoff;
                uint2 h0 = f4h(rb[0]), h1 = f4h(rb[1]), h2 = f4h(rb[2]), h3 = f4h(rb[3]);
                *(uint4*)(bd)      = make_uint4(h0.x, h0.y, h1.x, h1.y);
                *(uint4*)(bd + 16) = make_uint4(h2.x, h2.y, h3.x, h3.y);
                CP_WAIT0();
            }
            __syncthreads();
        }

#pragma unroll
        for (int mi = 0; mi < 2; ++mi) {
            int rA = m0 + (mt0 + mi) * 16 + gid;
            int rB = rA + 8;
#pragma unroll
            for (int ni = 0; ni < 4; ++ni) {
                int col = n0 + (wn + ni) * 8 + 2 * tig;
                if (rA < Mloc) {
                    __half2 h = __floats2half2_rn(
                        silu_mul(accg[mi][ni][0], accu[mi][ni][0]),
                        silu_mul(accg[mi][ni][1], accu[mi][ni][1]));
                    *(__half2*)&Cp[(long long)rA * ldc + col] = h;
                }
                if (rB < Mloc) {
                    __half2 h = __floats2half2_rn(
                        silu_mul(accg[mi][ni][2], accu[mi][ni][2]),
                        silu_mul(accg[mi][ni][3], accu[mi][ni][3]));
                    *(__half2*)&Cp[(long long)rB * ldc + col] = h;
                }
            }
        }
    }

    // publish completion
    __threadfence();
    __syncthreads();
    if (threadIdx.x == 0) {
        if (routed) atomicAdd(&g_done[e], 1);
        else        atomicAdd(&g_done_sh, 1);
    }
}

// ============================================================================
// Plain tile (R13 body). Block M=128, N=128.
// ============================================================================
__device__ __forceinline__ void plain_tile(char* sm, int idx,
                                           const float* __restrict__ w2,
                                           const float* __restrict__ sdn,
                                           float* __restrict__ out) {
    const bool routed = idx < PLAIN_ROUTED_TILES;
    int e, nt, mt, Mloc, lda, ldb, ldc, Kd, need;
    const float*  Bp;
    const __half* Ap;
    float* Cp;
    int* dep;
    if (routed) {
        e = idx / 32; int r = idx % 32;
        nt = r % 16; mt = r / 16;
        Mloc = g_counts[e];
        Ap = g_h1 + (long long)e * CAP * IDIM;  lda = IDIM;
        Bp = w2  + (long long)e * IDIM * HDIM;  ldb = HDIM;
        Cp = g_y + (long long)e * CAP * HDIM;   ldc = HDIM;
        Kd = IDIM;
        dep = &g_done[e]; need = 44;
    } else {
        e = 0; int r = idx - PLAIN_ROUTED_TILES;
        nt = r % 16; mt = r / 16;
        Mloc = T;
        Ap = g_hs; lda = ISH;
        Bp = sdn;  ldb = HDIM;
        Cp = out;  ldc = HDIM;
        Kd = ISH;
        dep = &g_done_sh; need = 176;
    }

    // wait for producer tiles
    if (threadIdx.x == 0) {
        while (atomicAdd(dep, 0) < need) __nanosleep(64);
    }
    __syncthreads();
    __threadfence();

    const int m0 = mt * 128;
    if (m0 >= Mloc) return;
    const int n0 = nt * 128;

    const unsigned smb  = (unsigned)__cvta_generic_to_shared(sm);
    const unsigned smbB = smb + 2 * A_STG;
    const int tid  = threadIdx.x;
    const int lane = tid & 31;
    const int wid  = tid >> 5;
    const int gid  = lane >> 2;
    const int tig  = lane & 3;
    const int mt0  = (wid >> 2) * 4;
    const int nt0  = (wid & 3) * 4;

    const int arow = tid >> 1;
    const int ah   = tid & 1;
    const int gm   = m0 + arow;
    const bool avl = gm < Mloc;
    const __half* asrc = Ap + (long long)(avl ? gm : 0) * lda + ah * 16;
    const unsigned adst = smb + (unsigned)arow * RSA + (unsigned)ah * 32u;
    const unsigned asz  = avl ? 16u : 0u;

    const int kk = tid >> 3;
    const int ng = tid & 7;
    const float* bsrc = Bp + (long long)kk * ldb + n0 + ng * 16;
    const unsigned bdoff = (unsigned)kk * RSB + (unsigned)ng * 32u;

    float acc[4][4][4];
#pragma unroll
    for (int mi = 0; mi < 4; ++mi)
#pragma unroll
        for (int ni = 0; ni < 4; ++ni)
#pragma unroll
            for (int r = 0; r < 4; ++r) acc[mi][ni][r] = 0.f;

    unsigned aAddr[4], bAddr[2];
#pragma unroll
    for (int mi = 0; mi < 4; ++mi)
        aAddr[mi] = smb + ((mt0 + mi) * 16 + (lane & 15)) * RSA + (lane >> 4) * 16;
#pragma unroll
    for (int j = 0; j < 2; ++j)
        bAddr[j] = smbB + (lane & 15) * RSB + (nt0 + 2 * j) * 16 + (lane >> 4) * 16;

    const int S = Kd / 32;
    float4 rb[4];

    cpa16(adst, asrc, asz);
    cpa16(adst + 16, asrc + 8, asz);
    CP_COMMIT();
#pragma unroll
    for (int q = 0; q < 4; ++q) rb[q] = ((const float4*)bsrc)[q];
    {
        char* bd = sm + 2 * A_STG + bdoff;
        uint2 h0 = f4h(rb[0]), h1 = f4h(rb[1]), h2 = f4h(rb[2]), h3 = f4h(rb[3]);
        *(uint4*)(bd)      = make_uint4(h0.x, h0.y, h1.x, h1.y);
        *(uint4*)(bd + 16) = make_uint4(h2.x, h2.y, h3.x, h3.y);
    }
    CP_WAIT0();
    __syncthreads();

    for (int s = 0; s < S; ++s) {
        const unsigned buf = s & 1;
        const bool nxt = (s + 1) < S;
        if (nxt) {
            const unsigned b2 = buf ^ 1;
            const __half* src = asrc + (s + 1) * 32;
            cpa16(adst + b2 * A_STG, src, asz);
            cpa16(adst + b2 * A_STG + 16, src + 8, asz);
            CP_COMMIT();
            const float* bs = bsrc + (long long)(s + 1) * 32 * ldb;
#pragma unroll
            for (int q = 0; q < 4; ++q) rb[q] = ((const float4*)bs)[q];
        }
        const unsigned ao = buf * A_STG, bo = buf * B_STG;
#pragma unroll
        for (int kt = 0; kt < 2; ++kt) {
            const unsigned ka = kt * 32, kb = kt * 16 * RSB;
            uint4 af[4];
#pragma unroll
            for (int mi = 0; mi < 4; ++mi) af[mi] = ldsm4(aAddr[mi] + ao + ka);
            uint4 b0 = ldsm4t(bAddr[0] + bo + kb);
            uint4 b1 = ldsm4t(bAddr[1] + bo + kb);
#pragma unroll
            for (int mi = 0; mi < 4; ++mi) {
                mma_f16(acc[mi][0], af[mi], b0.x, b0.y);
                mma_f16(acc[mi][1], af[mi], b0.z, b0.w);
                mma_f16(acc[mi][2], af[mi], b1.x, b1.y);
                mma_f16(acc[mi][3], af[mi], b1.z, b1.w);
            }
        }
        if (nxt) {
            char* bd = sm + 2 * A_STG + (buf ^ 1) * B_STG + bdoff;
            uint2 h0 = f4h(rb[0]), h1 = f4h(rb[1]), h2 = f4h(rb[2]), h3 = f4h(rb[3]);
            *(uint4*)(bd)      = make_uint4(h0.x, h0.y, h1.x, h1.y);
            *(uint4*)(bd + 16) = make_uint4(h2.x, h2.y, h3.x, h3.y);
            CP_WAIT0();
        }
        __syncthreads();
    }

#pragma unroll
    for (int mi = 0; mi < 4; ++mi) {
        int rA = m0 + (mt0 + mi) * 16 + gid;
        int rB = rA + 8;
#pragma unroll
        for (int ni = 0; ni < 4; ++ni) {
            int c0 = n0 + (nt0 + ni) * 8 + 2 * tig;
            if (rA < Mloc)
                *(float2*)&Cp[(long long)rA * ldc + c0] =
                    make_float2(acc[mi][ni][0], acc[mi][ni][1]);
            if (rB < Mloc)
                *(float2*)&Cp[(long long)rB * ldc + c0] =
                    make_float2(acc[mi][ni][2], acc[mi][ni][3]);
        }
    }
}

// ============================================================================
// Persistent mega-kernel: work queue over fused tiles then plain tiles.
// ============================================================================
__global__ void __launch_bounds__(256, 2)
moe_mega(const float* __restrict__ w13, const float* __restrict__ sgu,
         const float* __restrict__ w2,  const float* __restrict__ sdn,
         float* __restrict__ out) {
    __shared__ __align__(16) char sm[2 * A_STG + 2 * B_STG];
    __shared__ int s_tile;

    for (;;) {
        if (threadIdx.x == 0) s_tile = atomicAdd(&g_queue, 1);
        __syncthreads();
        const int tile = s_tile;
        if (tile >= TOTAL_TILES) return;
        if (tile < FUSED_TILES) fused_tile(sm, tile, w13, sgu);
        else                    plain_tile(sm, tile - FUSED_TILES, w2, sdn, out);
        __syncthreads();
    }
}

// ---------------- combine (float4) ----------------
__global__ void combine_kernel(float* __restrict__ out) {
    int t = blockIdx.x;
    __shared__ int   sslot[TOPK];
    __shared__ float sw[TOPK];
    if (threadIdx.x < TOPK) {
        sslot[threadIdx.x] = g_assign_slot[t * TOPK + threadIdx.x];
        sw[threadIdx.x]    = g_topk_w[t * TOPK + threadIdx.x];
    }
    __syncthreads();
    for (int h = threadIdx.x * 4; h < HDIM; h += 256 * 4) {
        float4 acc = *(float4*)&out[(long long)t * HDIM + h];
#pragma unroll
        for (int k = 0; k < TOPK; ++k) {
            int sl = sslot[k];
            if (sl >= 0) {
                float4 y = *(float4*)&g_y[(long long)sl * HDIM + h];
                float w = sw[k];
                acc.x += w * y.x; acc.y += w * y.y;
                acc.z += w * y.z; acc.w += w * y.w;
            }
        }
        *(float4*)&out[(long long)t * HDIM + h] = acc;
    }
}

// ---------------- launch ----------------
extern "C" void kernel_launch(void* const* d_in, const int* in_sizes, int n_in,
                              void* d_out, int out_size) {
    const float* x     = (const float*)d_in[0];
    const float* gw    = (const float*)d_in[2];
    const float* bias  = (const float*)d_in[3];
    const float* w13   = (const float*)d_in[4];
    const float* w2    = (const float*)d_in[5];
    const float* sgu   = (const float*)d_in[6];
    const float* sdn   = (const float*)d_in[7];
    float* out = (float*)d_out;

    convert_x<<<T * HDIM / 1024, 256>>>(x);
    routing_kernel<<<T, 256>>>(x, gw, bias);
    rank_kernel<<<1, 1024>>>();
    moe_mega<<<PERSIST_BLKS, 256>>>(w13, sgu, w2, sdn, out);
    combine_kernel<<<T, 256>>>(out);
}